// round 6
// baseline (speedup 1.0000x reference)
#include <cuda_runtime.h>
#include <cuda_bf16.h>
#include <float.h>

#define MAX_N 8192
#define BLOCK 256
#define WARPS_PER_ROW 2
#define ROWS_PER_BLOCK 4                      // 8 warps / 2 per row
#define GRID (MAX_N / ROWS_PER_BLOCK)         // 2048

__device__ float        g_block_sum[GRID];
__device__ unsigned int g_done_count = 0;     // self-resets via atomicInc wrap

__global__ __launch_bounds__(BLOCK, 8)        // regs<=32 -> 8 blocks/SM -> 64 warps
void triplet_fused_kernel(const float* __restrict__ sim,
                          const int* __restrict__ targets,
                          const int* __restrict__ idx,
                          float* __restrict__ out,
                          int n) {
    __shared__ float s_pos[BLOCK / 32];
    __shared__ float s_neg[BLOCK / 32];
    __shared__ float s_loss[ROWS_PER_BLOCK];
    __shared__ unsigned int s_is_last;

    const int tid  = threadIdx.x;
    const int wid  = tid >> 5;                // 0..7
    const int lid  = tid & 31;
    const int rloc = wid >> 1;                // row within block: 0..3
    const int half = wid & 1;                 // which half-row this warp streams

    const int row = blockIdx.x * ROWS_PER_BLOCK + rloc;
    const int my_t = targets[row];
    const int self_col = idx[row];
    const float* __restrict__ rp = sim + (size_t)self_col * (size_t)n;
    const int4* __restrict__ tp = reinterpret_cast<const int4*>(targets);

    const int jbeg = half * (n >> 1);         // 0 or 4096

    float pos =  FLT_MAX;
    float neg = -FLT_MAX;

    // Warp streams its 16 KB half-row; unroll 4 keeps 4 LDG.128 in flight.
    #pragma unroll 4
    for (int it = 0; it < (n / 2) / (32 * 4); it++) {
        const int j = jbeg + it * 128 + lid * 4;
        const float4 v = __ldcs(reinterpret_cast<const float4*>(rp + j));
        const int4   t = tp[j >> 2];

        if (t.x == my_t) { if (j + 0 != self_col) pos = fminf(pos, v.x); }
        else             { neg = fmaxf(neg, v.x); }
        if (t.y == my_t) { if (j + 1 != self_col) pos = fminf(pos, v.y); }
        else             { neg = fmaxf(neg, v.y); }
        if (t.z == my_t) { if (j + 2 != self_col) pos = fminf(pos, v.z); }
        else             { neg = fmaxf(neg, v.z); }
        if (t.w == my_t) { if (j + 3 != self_col) pos = fminf(pos, v.w); }
        else             { neg = fmaxf(neg, v.w); }
    }

    // Warp reduction.
    #pragma unroll
    for (int off = 16; off > 0; off >>= 1) {
        pos = fminf(pos, __shfl_xor_sync(0xFFFFFFFFu, pos, off));
        neg = fmaxf(neg, __shfl_xor_sync(0xFFFFFFFFu, neg, off));
    }
    if (lid == 0) { s_pos[wid] = pos; s_neg[wid] = neg; }
    __syncthreads();

    // One thread per row combines its two half-row partials.
    if (tid < ROWS_PER_BLOCK) {
        const int w0 = tid * 2;
        const float p = fminf(s_pos[w0], s_pos[w0 + 1]);
        const float g = fmaxf(s_neg[w0], s_neg[w0 + 1]);
        s_loss[tid] = fmaxf(g - p + 0.1f, 0.0f);
    }
    __syncthreads();

    // Block sum in FIXED order -> deterministic.
    if (tid == 0) {
        float bs = 0.0f;
        #pragma unroll
        for (int r = 0; r < ROWS_PER_BLOCK; r++) bs += s_loss[r];
        g_block_sum[blockIdx.x] = bs;
        __threadfence();
        unsigned int prev = atomicInc(&g_done_count, GRID - 1);
        s_is_last = (prev == GRID - 1) ? 1u : 0u;
    }
    __syncthreads();

    // Last block reduces the 2048 partials in fixed tree order.
    if (s_is_last) {
        __shared__ float s_sum[BLOCK / 32];
        // 2048 floats = 512 float4; 256 threads x 2 float4.
        const float4* bp = reinterpret_cast<const float4*>(g_block_sum);
        float4 a = __ldcg(bp + tid);
        float4 b = __ldcg(bp + tid + 256);
        float acc = ((a.x + a.y) + (a.z + a.w)) + ((b.x + b.y) + (b.z + b.w));
        #pragma unroll
        for (int off = 16; off > 0; off >>= 1)
            acc += __shfl_xor_sync(0xFFFFFFFFu, acc, off);
        if (lid == 0) s_sum[wid] = acc;
        __syncthreads();
        if (wid == 0) {
            acc = (lid < BLOCK / 32) ? s_sum[lid] : 0.0f;
            #pragma unroll
            for (int off = 4; off > 0; off >>= 1)
                acc += __shfl_xor_sync(0xFFFFFFFFu, acc, off);
            if (lid == 0) out[0] = acc / (float)n;
        }
    }
}

extern "C" void kernel_launch(void* const* d_in, const int* in_sizes, int n_in,
                              void* d_out, int out_size) {
    const float* sim     = (const float*)d_in[0];
    const int*   targets = (const int*)d_in[1];
    const int*   idx     = (const int*)d_in[2];
    float* out = (float*)d_out;

    const int n = in_sizes[1];   // 8192

    triplet_fused_kernel<<<GRID, BLOCK>>>(sim, targets, idx, out, n);
}